// round 1
// baseline (speedup 1.0000x reference)
#include <cuda_runtime.h>
#include <math.h>

// Problem constants (B,T,I,H,O fixed by the dataset)
#define BDIM 128
#define TDIM 512
#define IDIM 4
#define HDIM 512
#define ODIM 3
#define NREGC 256          // round(H * 0.5)

// Grid decomposition: 8 M-tiles x 16 N-tiles = 128 co-resident CTAs
#define GM 8
#define GN 16
#define GRID (GM * GN)     // 128
#define NTHREADS 256
#define MT (BDIM / GM)     // 16 rows per CTA
#define NT (HDIM / GN)     // 32 cols per CTA
#define WPAD 516           // padded row stride for W slice in smem (bank-conflict-free float4)

#define SMEM_FLOATS (NT * WPAD + MT * HDIM)
#define SMEM_BYTES (SMEM_FLOATS * 4)   // 98816 B

// Scratch in device globals (no allocations allowed)
__device__ float     g_th[2][BDIM * HDIM];   // tanh(h) double buffer
__device__ unsigned  g_flags[GRID];          // grid barrier flags (monotonic epochs)
__device__ float     g_regpart[GRID];        // per-CTA regularizer partials

__device__ __forceinline__ void grid_barrier(unsigned target, int tid, int bx)
{
    __syncthreads();
    if (tid == 0) {
        __threadfence();
        *((volatile unsigned*)&g_flags[bx]) = target;
    }
    if (tid < 32) {
        for (int i = tid; i < GRID; i += 32) {
            while ((int)(*((volatile unsigned*)&g_flags[i]) - target) < 0) { }
        }
        __threadfence();
    }
    __syncthreads();
}

__global__ __launch_bounds__(NTHREADS, 1)
void rnn_persistent_kernel(const float* __restrict__ x,      // (B,T,I)
                           const float* __restrict__ h0,     // (B,H)
                           const float* __restrict__ Wrec,   // (H,H) row k, col n
                           const float* __restrict__ Win,    // (I,H)
                           const float* __restrict__ Wout,   // (H,O)
                           const float* __restrict__ brec,   // (H)
                           const float* __restrict__ bin,    // (H)
                           float* __restrict__ out)
{
    extern __shared__ float smem[];
    float* Wsm = smem;                 // [NT][WPAD]  (n-major, k fast) persistent W_rec slice
    float* Asm = smem + NT * WPAD;     // [MT][HDIM]  per-step tanh(h) stage

    const int tid  = threadIdx.x;
    const int w    = tid >> 5;
    const int lane = tid & 31;
    const int bx   = blockIdx.x;
    const int gm   = bx / GN;
    const int gn   = bx % GN;

    const int b0 = gm * MT + 2 * w;    // two rows owned by this thread: b0, b0+1
    const int n  = gn * NT + lane;     // one column owned by this thread

    float* out_y   = out;                                   // (B,T,O)
    float* out_hs  = out + (size_t)BDIM * TDIM * ODIM;      // (T+1,B,H)
    float* out_reg = out_hs + (size_t)(TDIM + 1) * BDIM * HDIM;

    // ---- barrier epoch base (flags all equal at launch; monotonic across replays) ----
    __shared__ unsigned s_base;
    __shared__ float    s_red[NTHREADS / 32];
    if (tid == 0) s_base = *((volatile unsigned*)&g_flags[bx]);
    __syncthreads();
    const unsigned base = s_base;
    unsigned barcnt = 0;

    // ---- stage W_rec slice into smem, transposed to [n_local][k] ----
    for (int idx = tid; idx < HDIM * NT; idx += NTHREADS) {
        int k = idx >> 5;          // idx / NT
        int j = idx & (NT - 1);    // idx % NT
        Wsm[j * WPAD + k] = Wrec[(size_t)k * HDIM + gn * NT + j];
    }

    // ---- persistent per-thread state ----
    const float win0 = Win[0 * HDIM + n];
    const float win1 = Win[1 * HDIM + n];
    const float win2 = Win[2 * HDIM + n];
    const float win3 = Win[3 * HDIM + n];
    const float bsum = brec[n] + bin[n];

    float hA = h0[(size_t)b0 * HDIM + n];
    float hB = h0[(size_t)(b0 + 1) * HDIM + n];
    float zpA = 0.0f, zpB = 0.0f;
    float racc = 0.0f;

    // hidden_states[0] = h0 ; th[0] = tanh(h0)
    out_hs[(size_t)b0 * HDIM + n]       = hA;
    out_hs[(size_t)(b0 + 1) * HDIM + n] = hB;
    g_th[0][b0 * HDIM + n]       = tanhf(hA);
    g_th[0][(b0 + 1) * HDIM + n] = tanhf(hB);

    grid_barrier(base + (++barcnt), tid, bx);

    // =========================== main recurrence ===========================
    for (int t = 0; t < TDIM; ++t) {
        // stage tanh(h_prev) rows for this M-tile
        {
            const float4* src = (const float4*)(g_th[t & 1] + (size_t)gm * MT * HDIM);
            float4* dst = (float4*)Asm;
            #pragma unroll
            for (int idx = tid; idx < MT * HDIM / 4; idx += NTHREADS)
                dst[idx] = src[idx];
        }
        __syncthreads();

        // z[b0..b0+1][n] = tanh(h_prev) @ W_rec  (K = 512)
        const float* A0 = Asm + (2 * w) * HDIM;
        const float* A1 = A0 + HDIM;
        const float* Wr = Wsm + lane * WPAD;
        float z0a = 0.f, z0b = 0.f, z1a = 0.f, z1b = 0.f;
        #pragma unroll 8
        for (int k = 0; k < HDIM; k += 4) {
            float4 a0 = *(const float4*)(A0 + k);
            float4 a1 = *(const float4*)(A1 + k);
            float4 wv = *(const float4*)(Wr + k);
            z0a = fmaf(a0.x, wv.x, z0a);
            z0b = fmaf(a0.y, wv.y, z0b);
            z0a = fmaf(a0.z, wv.z, z0a);
            z0b = fmaf(a0.w, wv.w, z0b);
            z1a = fmaf(a1.x, wv.x, z1a);
            z1b = fmaf(a1.y, wv.y, z1b);
            z1a = fmaf(a1.z, wv.z, z1a);
            z1b = fmaf(a1.w, wv.w, z1b);
        }

        // input drive + biases
        float4 xv0 = *(const float4*)(x + ((size_t)b0 * TDIM + t) * IDIM);
        float4 xv1 = *(const float4*)(x + ((size_t)(b0 + 1) * TDIM + t) * IDIM);
        float zA = (z0a + z0b) + bsum;
        float zB = (z1a + z1b) + bsum;
        zA = fmaf(xv0.x, win0, zA); zA = fmaf(xv0.y, win1, zA);
        zA = fmaf(xv0.z, win2, zA); zA = fmaf(xv0.w, win3, zA);
        zB = fmaf(xv1.x, win0, zB); zB = fmaf(xv1.y, win1, zB);
        zB = fmaf(xv1.z, win2, zB); zB = fmaf(xv1.w, win3, zB);

        // leaky update (alpha = 0.5)
        float hnA = 0.5f * (hA + zA);
        float hnB = 0.5f * (hB + zB);

        // regularizer partials (first NREGC columns)
        if (n < NREGC) {
            float dA = hnA - hA, dB = hnB - hB;
            racc = fmaf(dA, dA, racc);
            racc = fmaf(dB, dB, racc);
            if (t > 0) {
                float eA = zA - zpA, eB = zB - zpB;
                racc = fmaf(eA, eA, racc);
                racc = fmaf(eB, eB, racc);
            }
        }

        // write hidden_states[t+1] and tanh double-buffer for next step
        size_t off = (size_t)(t + 1) * BDIM * HDIM;
        out_hs[off + (size_t)b0 * HDIM + n]       = hnA;
        out_hs[off + (size_t)(b0 + 1) * HDIM + n] = hnB;
        float* thn = g_th[(t + 1) & 1];
        thn[b0 * HDIM + n]       = tanhf(hnA);
        thn[(b0 + 1) * HDIM + n] = tanhf(hnB);

        hA = hnA; hB = hnB; zpA = zA; zpB = zB;

        grid_barrier(base + (++barcnt), tid, bx);
    }

    // =========================== regularizer reduction ===========================
    float r = racc;
    #pragma unroll
    for (int off = 16; off; off >>= 1) r += __shfl_xor_sync(0xffffffffu, r, off);
    if (lane == 0) s_red[w] = r;
    __syncthreads();
    if (tid == 0) {
        float s = 0.f;
        #pragma unroll
        for (int i = 0; i < NTHREADS / 32; ++i) s += s_red[i];
        g_regpart[bx] = s;
    }
    grid_barrier(base + (++barcnt), tid, bx);
    if (bx == 0 && tid == 0) {
        float s = 0.f;
        for (int i = 0; i < GRID; ++i) s += g_regpart[i];
        *out_reg = s / ((float)TDIM * (float)BDIM * (float)NREGC);
    }

    // =========================== outputs epilogue: out[b,t] = h[t+1,b] @ W_out ===========================
    // stage W_out (H x 3) into smem, float4-padded; Asm region reused
    float* WoutS = Asm;
    for (int kk = tid; kk < HDIM; kk += NTHREADS) {
        WoutS[kk * 4 + 0] = Wout[kk * 3 + 0];
        WoutS[kk * 4 + 1] = Wout[kk * 3 + 1];
        WoutS[kk * 4 + 2] = Wout[kk * 3 + 2];
        WoutS[kk * 4 + 3] = 0.f;
    }
    __syncthreads();

    const int gw = bx * (NTHREADS / 32) + w;           // global warp id, 0..1023
    for (int p = gw; p < BDIM * TDIM; p += GRID * (NTHREADS / 32)) {
        int tt = p >> 7;          // p / 128
        int bb = p & 127;         // p % 128
        const float* row = out_hs + (size_t)(tt + 1) * BDIM * HDIM + (size_t)bb * HDIM;
        float o0 = 0.f, o1 = 0.f, o2 = 0.f;
        #pragma unroll 4
        for (int k = lane; k < HDIM; k += 32) {
            float  hv = row[k];
            float4 wv = ((const float4*)WoutS)[k];
            o0 = fmaf(hv, wv.x, o0);
            o1 = fmaf(hv, wv.y, o1);
            o2 = fmaf(hv, wv.z, o2);
        }
        #pragma unroll
        for (int off = 16; off; off >>= 1) {
            o0 += __shfl_xor_sync(0xffffffffu, o0, off);
            o1 += __shfl_xor_sync(0xffffffffu, o1, off);
            o2 += __shfl_xor_sync(0xffffffffu, o2, off);
        }
        if (lane == 0) {
            float* dst = out_y + ((size_t)bb * TDIM + tt) * ODIM;
            dst[0] = o0; dst[1] = o1; dst[2] = o2;
        }
    }
}

extern "C" void kernel_launch(void* const* d_in, const int* in_sizes, int n_in,
                              void* d_out, int out_size)
{
    (void)in_sizes; (void)n_in; (void)out_size;
    const float* x    = (const float*)d_in[0];
    const float* h0   = (const float*)d_in[1];
    const float* Wrec = (const float*)d_in[2];
    const float* Win  = (const float*)d_in[3];
    const float* Wout = (const float*)d_in[4];
    const float* brec = (const float*)d_in[5];
    const float* bin  = (const float*)d_in[6];
    float* out = (float*)d_out;

    cudaFuncSetAttribute(rnn_persistent_kernel,
                         cudaFuncAttributeMaxDynamicSharedMemorySize, SMEM_BYTES);

    rnn_persistent_kernel<<<GRID, NTHREADS, SMEM_BYTES>>>(
        x, h0, Wrec, Win, Wout, brec, bin, out);
}